// round 6
// baseline (speedup 1.0000x reference)
#include <cuda_runtime.h>
#include <cuda_bf16.h>
#include <cstdint>

#define T_ 4096
#define B_ 4
#define C_ 1024
#define MT_ (B_*T_)

#define BM 256
#define BN 128
#define NTHR 512
#define STAGE_BYTES 98304          // A hi/lo 2x32KB + B hi/lo 2x16KB
#define SMEM_DYN (2*STAGE_BYTES + 1024)

// ---------------- scratch (device globals; no cudaMalloc allowed) ----------
__device__ __align__(16) __nv_bfloat16 g_xhi[(size_t)MT_*C_];
__device__ __align__(16) __nv_bfloat16 g_xlo[(size_t)MT_*C_];
__device__ __align__(16) __nv_bfloat16 g_Whi[(size_t)4*C_*C_];
__device__ __align__(16) __nv_bfloat16 g_Wlo[(size_t)4*C_*C_];
__device__ __align__(16) __nv_bfloat16 g_Qhi[(size_t)MT_*C_];
__device__ __align__(16) __nv_bfloat16 g_Qlo[(size_t)MT_*C_];
__device__ __align__(16) __nv_bfloat16 g_Khi[(size_t)MT_*C_];
__device__ __align__(16) __nv_bfloat16 g_Klo[(size_t)MT_*C_];
__device__ __align__(16) __nv_bfloat16 g_Vthi[(size_t)MT_*C_];  // [B][C][T]
__device__ __align__(16) __nv_bfloat16 g_Vtlo[(size_t)MT_*C_];
__device__ __align__(16) float         g_S  [(size_t)B_*T_*T_];
__device__ __align__(16) __nv_bfloat16 g_Phi[(size_t)B_*T_*T_];
__device__ __align__(16) __nv_bfloat16 g_Plo[(size_t)B_*T_*T_];
__device__ __align__(16) __nv_bfloat16 g_AOhi[(size_t)MT_*C_];
__device__ __align__(16) __nv_bfloat16 g_AOlo[(size_t)MT_*C_];

extern __shared__ char dyn_smem[];

// ---------------- helpers ----------------------------------------------------
static __device__ __forceinline__ uint32_t smem_u32(const void* p){
  uint32_t a;
  asm("{ .reg .u64 t; cvta.to.shared.u64 t, %1; cvt.u32.u64 %0, t; }" : "=r"(a) : "l"(p));
  return a;
}
static __device__ __forceinline__ uint32_t swz(uint32_t o){ return o ^ ((o>>3)&0x70u); }

static __device__ __forceinline__ void ldsm4(uint32_t addr,
    uint32_t &r0, uint32_t &r1, uint32_t &r2, uint32_t &r3){
  asm volatile("ldmatrix.sync.aligned.m8n8.x4.shared.b16 {%0,%1,%2,%3}, [%4];"
    : "=r"(r0), "=r"(r1), "=r"(r2), "=r"(r3) : "r"(addr));
}
static __device__ __forceinline__ void mma16816(float* c,
    const uint32_t* a, const uint32_t* b){
  asm volatile("mma.sync.aligned.m16n8k16.row.col.f32.bf16.bf16.f32 "
    "{%0,%1,%2,%3}, {%4,%5,%6,%7}, {%8,%9}, {%0,%1,%2,%3};"
    : "+f"(c[0]), "+f"(c[1]), "+f"(c[2]), "+f"(c[3])
    : "r"(a[0]), "r"(a[1]), "r"(a[2]), "r"(a[3]), "r"(b[0]), "r"(b[1]));
}

// ROWS x 64 bf16 tile -> SW128-swizzled smem (NTHR=512 threads)
// total cp.async ops = ROWS*64*2/16 = ROWS*8; iterations = ROWS*8/512 = ROWS/64
template<int ROWS>
static __device__ __forceinline__ void cp_tile(uint32_t sb,
    const __nv_bfloat16* __restrict__ g, int ldk){
  const int t = threadIdx.x;
#pragma unroll
  for (int i = 0; i < ROWS/64; ++i){
    int q = t + (i<<9);
    int row = q>>3, gr = q&7;
    const __nv_bfloat16* src = g + (size_t)row*ldk + (gr<<3);
    uint32_t dst = sb + swz((uint32_t)((row<<7)|(gr<<4)));
    asm volatile("cp.async.cg.shared.global [%0], [%1], 16;"
                 :: "r"(dst), "l"(src) : "memory");
  }
}
static __device__ __forceinline__ void cp_stage(uint32_t st,
    const __nv_bfloat16* Ahi, const __nv_bfloat16* Alo, int lda,
    const __nv_bfloat16* Bhi, const __nv_bfloat16* Blo, int ldb, int kt){
  cp_tile<256>(st +     0, Ahi + kt, lda);
  cp_tile<256>(st + 32768, Alo + kt, lda);
  cp_tile<128>(st + 65536, Bhi + kt, ldb);
  cp_tile<128>(st + 81920, Blo + kt, ldb);
}

// ---- core: acc[256,128] += (Ahi+Alo)[256,K] @ ((Bhi+Blo)[128,K])^T ---------
// 16 warps: wm = wid>>2 (4 x 64 rows), wn = wid&3 (4 x 32 cols); warp 64x32
static __device__ __forceinline__ void hgemm_core(
    float (&acc)[4][4][4],
    const __nv_bfloat16* Ahi, const __nv_bfloat16* Alo, int lda,
    const __nv_bfloat16* Bhi, const __nv_bfloat16* Blo, int ldb, int K)
{
  const uint32_t sb = (smem_u32(dyn_smem) + 1023u) & ~1023u;
  const int tid = threadIdx.x, lane = tid&31, wid = tid>>5;
  const int wm = wid>>2, wn = wid&3;
  const int l7 = lane&7, sel = lane>>3;
  const int a_r = l7 + ((sel&1)<<3), a_g = sel>>1;
  const int b_r = l7 + ((sel>>1)<<3), b_g = sel&1;

  const int nc = K >> 6;
  cp_stage(sb, Ahi, Alo, lda, Bhi, Blo, ldb, 0);
  asm volatile("cp.async.commit_group;" ::: "memory");

  for (int c = 0; c < nc; ++c){
    const uint32_t st = sb + (uint32_t)(c&1)*STAGE_BYTES;
    if (c + 1 < nc){
      cp_stage(sb + (uint32_t)((c+1)&1)*STAGE_BYTES,
               Ahi, Alo, lda, Bhi, Blo, ldb, (c+1)<<6);
      asm volatile("cp.async.commit_group;" ::: "memory");
      asm volatile("cp.async.wait_group 1;" ::: "memory");
    } else {
      asm volatile("cp.async.wait_group 0;" ::: "memory");
    }
    __syncthreads();

#pragma unroll
    for (int ks = 0; ks < 4; ++ks){
      uint32_t bh[4][2], bl[4][2];
#pragma unroll
      for (int nn2 = 0; nn2 < 2; ++nn2){
        uint32_t bd = swz((uint32_t)(((wn*32 + nn2*16 + b_r)<<7) | ((ks*2 + b_g)<<4)));
        uint32_t r0, r1, r2, r3;
        ldsm4(st + 65536 + bd, r0, r1, r2, r3);
        bh[nn2*2][0]=r0; bh[nn2*2][1]=r1; bh[nn2*2+1][0]=r2; bh[nn2*2+1][1]=r3;
        ldsm4(st + 81920 + bd, r0, r1, r2, r3);
        bl[nn2*2][0]=r0; bl[nn2*2][1]=r1; bl[nn2*2+1][0]=r2; bl[nn2*2+1][1]=r3;
      }
#pragma unroll
      for (int mm = 0; mm < 4; ++mm){
        uint32_t ah[4], al[4];
        uint32_t ad = swz((uint32_t)(((wm*64 + mm*16 + a_r)<<7) | ((ks*2 + a_g)<<4)));
        ldsm4(st +         ad, ah[0], ah[1], ah[2], ah[3]);
        ldsm4(st + 32768 + ad, al[0], al[1], al[2], al[3]);
#pragma unroll
        for (int nn = 0; nn < 4; ++nn){
          float* a = acc[mm][nn];
          mma16816(a, ah, bh[nn]);
          mma16816(a, ah, bl[nn]);
          mma16816(a, al, bh[nn]);
        }
      }
    }
    if (c + 1 < nc) __syncthreads();
  }
}

static __device__ __forceinline__ void split_store2(
    __nv_bfloat16* H, __nv_bfloat16* L, size_t idx, float a, float b){
  __nv_bfloat16 ah = __float2bfloat16_rn(a), bh = __float2bfloat16_rn(b);
  __nv_bfloat16 alo = __float2bfloat16_rn(a - __bfloat162float(ah));
  __nv_bfloat16 blo = __float2bfloat16_rn(b - __bfloat162float(bh));
  *reinterpret_cast<__nv_bfloat162*>(H + idx) = __halves2bfloat162(ah, bh);
  *reinterpret_cast<__nv_bfloat162*>(L + idx) = __halves2bfloat162(alo, blo);
}
static __device__ __forceinline__ void split_store1(
    __nv_bfloat16* H, __nv_bfloat16* L, size_t idx, float a){
  __nv_bfloat16 ah = __float2bfloat16_rn(a);
  H[idx] = ah;
  L[idx] = __float2bfloat16_rn(a - __bfloat162float(ah));
}

// ---------------- fp32 -> split bf16 ---------------------------------------
__global__ __launch_bounds__(256) void split_k(
    const float* __restrict__ s, __nv_bfloat16* __restrict__ hi,
    __nv_bfloat16* __restrict__ lo)
{
  size_t i = ((size_t)blockIdx.x*256 + threadIdx.x)*4;
  float4 v = *reinterpret_cast<const float4*>(s + i);
  float f[4] = {v.x, v.y, v.z, v.w};
  __nv_bfloat16 h[4], l[4];
#pragma unroll
  for (int k = 0; k < 4; ++k){
    h[k] = __float2bfloat16_rn(f[k]);
    l[k] = __float2bfloat16_rn(f[k] - __bfloat162float(h[k]));
  }
  reinterpret_cast<__nv_bfloat162*>(hi + i)[0] = __halves2bfloat162(h[0], h[1]);
  reinterpret_cast<__nv_bfloat162*>(hi + i)[1] = __halves2bfloat162(h[2], h[3]);
  reinterpret_cast<__nv_bfloat162*>(lo + i)[0] = __halves2bfloat162(l[0], l[1]);
  reinterpret_cast<__nv_bfloat162*>(lo + i)[1] = __halves2bfloat162(l[2], l[3]);
}

// ---------------- GEMM kernels ----------------------------------------------
__global__ __launch_bounds__(NTHR, 1) void qkv_tc()
{
  const int z = blockIdx.z, m0 = blockIdx.y<<8, n0 = blockIdx.x<<7;
  const size_t wo = (size_t)z*C_*C_;
  float acc[4][4][4] = {};
  hgemm_core(acc, g_xhi + (size_t)m0*C_, g_xlo + (size_t)m0*C_, C_,
             g_Whi + wo + (size_t)n0*C_, g_Wlo + wo + (size_t)n0*C_, C_, C_);

  const int lane = threadIdx.x&31, wid = threadIdx.x>>5;
  const int wm = wid>>2, wn = wid&3;
  const int rb = lane>>2, cb = (lane&3)*2;
#pragma unroll
  for (int mm = 0; mm < 4; ++mm)
#pragma unroll
    for (int nn = 0; nn < 4; ++nn){
      const int r  = m0 + wm*64 + mm*16 + rb;
      const int cc = n0 + wn*32 + nn*8 + cb;
      const float* a = acc[mm][nn];
      if (z == 2){                                   // V transposed: [b][c][t]
        const int b = r>>12, ml = r&(T_-1);
        size_t col0 = ((size_t)b*C_ + cc)*T_;
        split_store1(g_Vthi, g_Vtlo, col0 + ml,        a[0]);
        split_store1(g_Vthi, g_Vtlo, col0 + T_ + ml,   a[1]);
        split_store1(g_Vthi, g_Vtlo, col0 + ml + 8,    a[2]);
        split_store1(g_Vthi, g_Vtlo, col0 + T_ + ml+8, a[3]);
      } else {
        __nv_bfloat16* H = (z == 0) ? g_Qhi : g_Khi;
        __nv_bfloat16* L = (z == 0) ? g_Qlo : g_Klo;
        size_t base = (size_t)r*C_ + cc;
        split_store2(H, L, base,          a[0], a[1]);
        split_store2(H, L, base + 8*C_,   a[2], a[3]);
      }
    }
}

__global__ __launch_bounds__(NTHR, 1) void scores_tc()
{
  if ((blockIdx.x>>1) > blockIdx.y) return;          // tile fully above diagonal
  const int bz = blockIdx.z, m0 = blockIdx.y<<8, n0 = blockIdx.x<<7;
  const size_t qb = ((size_t)bz*T_ + m0)*C_;
  const size_t kb = ((size_t)bz*T_ + n0)*C_;
  float acc[4][4][4] = {};
  hgemm_core(acc, g_Qhi + qb, g_Qlo + qb, C_, g_Khi + kb, g_Klo + kb, C_, C_);

  const int lane = threadIdx.x&31, wid = threadIdx.x>>5;
  const int wm = wid>>2, wn = wid&3;
  const int rb = lane>>2, cb = (lane&3)*2;
#pragma unroll
  for (int mm = 0; mm < 4; ++mm)
#pragma unroll
    for (int nn = 0; nn < 4; ++nn){
      const int r  = m0 + wm*64 + mm*16 + rb;
      const int cc = n0 + wn*32 + nn*8 + cb;
      const float* a = acc[mm][nn];
      float* p = g_S + ((size_t)bz*T_ + r)*T_ + cc;
      *reinterpret_cast<float2*>(p)            = make_float2(a[0], a[1]);
      *reinterpret_cast<float2*>(p + 8ull*T_)  = make_float2(a[2], a[3]);
    }
}

__global__ __launch_bounds__(NTHR, 1) void pv_tc()
{
  const int bz = blockIdx.z, m0 = blockIdx.y<<8, n0 = blockIdx.x<<7;
  const int K  = m0 + 256;
  const size_t pb = ((size_t)bz*T_ + m0)*T_;
  const size_t vb = ((size_t)bz*C_ + n0)*T_;
  float acc[4][4][4] = {};
  hgemm_core(acc, g_Phi + pb, g_Plo + pb, T_, g_Vthi + vb, g_Vtlo + vb, T_, K);

  const int lane = threadIdx.x&31, wid = threadIdx.x>>5;
  const int wm = wid>>2, wn = wid&3;
  const int rb = lane>>2, cb = (lane&3)*2;
#pragma unroll
  for (int mm = 0; mm < 4; ++mm)
#pragma unroll
    for (int nn = 0; nn < 4; ++nn){
      const int r  = m0 + wm*64 + mm*16 + rb;
      const int cc = n0 + wn*32 + nn*8 + cb;
      const float* a = acc[mm][nn];
      size_t base = ((size_t)bz*T_ + r)*C_ + cc;
      split_store2(g_AOhi, g_AOlo, base,        a[0], a[1]);
      split_store2(g_AOhi, g_AOlo, base + 8*C_, a[2], a[3]);
    }
}

__global__ __launch_bounds__(NTHR, 1) void out_tc(const float* __restrict__ bo,
                                                  float* __restrict__ out)
{
  const int m0 = blockIdx.y<<8, n0 = blockIdx.x<<7;
  const size_t wo = (size_t)3*C_*C_;
  float acc[4][4][4] = {};
  hgemm_core(acc, g_AOhi + (size_t)m0*C_, g_AOlo + (size_t)m0*C_, C_,
             g_Whi + wo + (size_t)n0*C_, g_Wlo + wo + (size_t)n0*C_, C_, C_);

  const int lane = threadIdx.x&31, wid = threadIdx.x>>5;
  const int wm = wid>>2, wn = wid&3;
  const int rb = lane>>2, cb = (lane&3)*2;
#pragma unroll
  for (int mm = 0; mm < 4; ++mm)
#pragma unroll
    for (int nn = 0; nn < 4; ++nn){
      const int r  = m0 + wm*64 + mm*16 + rb;
      const int cc = n0 + wn*32 + nn*8 + cb;
      const float* a = acc[mm][nn];
      const float b0 = bo[cc], b1 = bo[cc+1];
      float* p = out + (size_t)r*C_ + cc;
      *reinterpret_cast<float2*>(p)          = make_float2(a[0]+b0, a[1]+b1);
      *reinterpret_cast<float2*>(p + 8*C_)   = make_float2(a[2]+b0, a[3]+b1);
    }
}

// ---------------- softmax: mask + scale + split-bf16 P ----------------------
__global__ __launch_bounds__(256) void softmax_k()
{
  const int gr = blockIdx.x;                 // 0..MT-1
  const int b  = gr >> 12, r = gr & (T_-1);
  const float* src = g_S + ((size_t)b*T_ + r)*T_;
  __nv_bfloat16* ph = g_Phi + ((size_t)b*T_ + r)*T_;
  __nv_bfloat16* pl = g_Plo + ((size_t)b*T_ + r)*T_;
  const int tid = threadIdx.x;
  const int nv  = r + 1;
  const int kmax = ((r >> 8) + 1) << 8;      // zero-pad to 256 (pv K granularity)
  const float scale = 0.03125f;              // 1/sqrt(1024)
  __shared__ float red[256];

  float m = __int_as_float(0xff800000);
  for (int c = tid; c < nv; c += 256) m = fmaxf(m, src[c]);
  red[tid] = m; __syncthreads();
  for (int s = 128; s > 0; s >>= 1){
    if (tid < s) red[tid] = fmaxf(red[tid], red[tid + s]);
    __syncthreads();
  }
  m = red[0]; __syncthreads();

  float sum = 0.f;
  for (int c = tid; c < nv; c += 256) sum += __expf((src[c] - m) * scale);
  red[tid] = sum; __syncthreads();
  for (int s = 128; s > 0; s >>= 1){
    if (tid < s) red[tid] += red[tid + s];
    __syncthreads();
  }
  const float inv = 1.f / red[0];

  for (int c = tid; c < kmax; c += 256){
    float p = (c < nv) ? __expf((src[c] - m) * scale) * inv : 0.f;
    __nv_bfloat16 h = __float2bfloat16_rn(p);
    ph[c] = h;
    pl[c] = __float2bfloat16_rn(p - __bfloat162float(h));
  }
}

// ---------------- launch -----------------------------------------------------
extern "C" void kernel_launch(void* const* d_in, const int* in_sizes, int n_in,
                              void* d_out, int out_size)
{
  const float* x  = (const float*)d_in[0];
  const float* Wq = (const float*)d_in[1];
  const float* Wk = (const float*)d_in[2];
  const float* Wv = (const float*)d_in[3];
  const float* Wo = (const float*)d_in[4];
  const float* bo = (const float*)d_in[5];
  float* out = (float*)d_out;
  (void)in_sizes; (void)n_in; (void)out_size;

  cudaFuncSetAttribute(qkv_tc,    cudaFuncAttributeMaxDynamicSharedMemorySize, SMEM_DYN);
  cudaFuncSetAttribute(scores_tc, cudaFuncAttributeMaxDynamicSharedMemorySize, SMEM_DYN);
  cudaFuncSetAttribute(pv_tc,     cudaFuncAttributeMaxDynamicSharedMemorySize, SMEM_DYN);
  cudaFuncSetAttribute(out_tc,    cudaFuncAttributeMaxDynamicSharedMemorySize, SMEM_DYN);

  __nv_bfloat16 *whi, *wlo, *xhi, *xlo;
  cudaGetSymbolAddress((void**)&whi, g_Whi);
  cudaGetSymbolAddress((void**)&wlo, g_Wlo);
  cudaGetSymbolAddress((void**)&xhi, g_xhi);
  cudaGetSymbolAddress((void**)&xlo, g_xlo);

  split_k<<<(size_t)MT_*C_/1024, 256>>>(x, xhi, xlo);
  split_k<<<(size_t)C_*C_/1024, 256>>>(Wq, whi + 0*(size_t)C_*C_, wlo + 0*(size_t)C_*C_);
  split_k<<<(size_t)C_*C_/1024, 256>>>(Wk, whi + 1*(size_t)C_*C_, wlo + 1*(size_t)C_*C_);
  split_k<<<(size_t)C_*C_/1024, 256>>>(Wv, whi + 2*(size_t)C_*C_, wlo + 2*(size_t)C_*C_);
  split_k<<<(size_t)C_*C_/1024, 256>>>(Wo, whi + 3*(size_t)C_*C_, wlo + 3*(size_t)C_*C_);

  qkv_tc   <<<dim3(C_/BN, MT_/BM, 3), NTHR, SMEM_DYN>>>();
  scores_tc<<<dim3(T_/BN, T_/BM, B_), NTHR, SMEM_DYN>>>();
  softmax_k<<<MT_, 256>>>();
  pv_tc    <<<dim3(C_/BN, T_/BM, B_), NTHR, SMEM_DYN>>>();
  out_tc   <<<dim3(C_/BN, MT_/BM, 1), NTHR, SMEM_DYN>>>(bo, out);
}

// round 7
// speedup vs baseline: 1.0997x; 1.0997x over previous
#include <cuda_runtime.h>
#include <cuda_bf16.h>
#include <cstdint>

#define T_ 4096
#define B_ 4
#define C_ 1024
#define MT_ (B_*T_)
#define STAGE_BYTES 65536
#define SMEM_DYN (3*STAGE_BYTES + 1024)

// ---------------- scratch (device globals; no cudaMalloc allowed) ----------
__device__ __align__(16) __nv_bfloat16 g_xhi[(size_t)MT_*C_];
__device__ __align__(16) __nv_bfloat16 g_xlo[(size_t)MT_*C_];
__device__ __align__(16) __nv_bfloat16 g_Whi[(size_t)4*C_*C_];
__device__ __align__(16) __nv_bfloat16 g_Wlo[(size_t)4*C_*C_];
__device__ __align__(16) __nv_bfloat16 g_Qhi[(size_t)MT_*C_];
__device__ __align__(16) __nv_bfloat16 g_Qlo[(size_t)MT_*C_];
__device__ __align__(16) __nv_bfloat16 g_Khi[(size_t)MT_*C_];
__device__ __align__(16) __nv_bfloat16 g_Klo[(size_t)MT_*C_];
__device__ __align__(16) __nv_bfloat16 g_Vthi[(size_t)MT_*C_];  // [B][C][T]
__device__ __align__(16) __nv_bfloat16 g_Vtlo[(size_t)MT_*C_];
__device__ __align__(16) float         g_S  [(size_t)B_*T_*T_];
__device__ __align__(16) __nv_bfloat16 g_Phi[(size_t)B_*T_*T_];
__device__ __align__(16) __nv_bfloat16 g_Plo[(size_t)B_*T_*T_];
__device__ __align__(16) __nv_bfloat16 g_AOhi[(size_t)MT_*C_];
__device__ __align__(16) __nv_bfloat16 g_AOlo[(size_t)MT_*C_];

extern __shared__ char dyn_smem[];

// ---------------- helpers ----------------------------------------------------
static __device__ __forceinline__ uint32_t smem_u32(const void* p){
  uint32_t a;
  asm("{ .reg .u64 t; cvta.to.shared.u64 t, %1; cvt.u32.u64 %0, t; }" : "=r"(a) : "l"(p));
  return a;
}
static __device__ __forceinline__ uint32_t swz(uint32_t o){ return o ^ ((o>>3)&0x70u); }

static __device__ __forceinline__ void ldsm4(uint32_t addr,
    uint32_t &r0, uint32_t &r1, uint32_t &r2, uint32_t &r3){
  asm volatile("ldmatrix.sync.aligned.m8n8.x4.shared.b16 {%0,%1,%2,%3}, [%4];"
    : "=r"(r0), "=r"(r1), "=r"(r2), "=r"(r3) : "r"(addr));
}
static __device__ __forceinline__ void mma16816(float* c,
    const uint32_t* a, const uint32_t* b){
  asm volatile("mma.sync.aligned.m16n8k16.row.col.f32.bf16.bf16.f32 "
    "{%0,%1,%2,%3}, {%4,%5,%6,%7}, {%8,%9}, {%0,%1,%2,%3};"
    : "+f"(c[0]), "+f"(c[1]), "+f"(c[2]), "+f"(c[3])
    : "r"(a[0]), "r"(a[1]), "r"(a[2]), "r"(a[3]), "r"(b[0]), "r"(b[1]));
}

// 128x64 bf16 tile (16KB) global -> SW128-swizzled smem (256 threads)
static __device__ __forceinline__ void cp_tile(uint32_t sb,
    const __nv_bfloat16* __restrict__ g, int ldk){
  const int t = threadIdx.x;
#pragma unroll
  for (int i = 0; i < 4; ++i){
    int q = t + (i<<8);
    int row = q>>3, gr = q&7;
    const __nv_bfloat16* src = g + (size_t)row*ldk + (gr<<3);
    uint32_t dst = sb + swz((uint32_t)((row<<7)|(gr<<4)));
    asm volatile("cp.async.cg.shared.global [%0], [%1], 16;"
                 :: "r"(dst), "l"(src) : "memory");
  }
}
static __device__ __forceinline__ void cp_stage(uint32_t st,
    const __nv_bfloat16* Ahi, const __nv_bfloat16* Alo, int lda,
    const __nv_bfloat16* Bhi, const __nv_bfloat16* Blo, int ldb, int kt){
  cp_tile(st +     0, Ahi + kt, lda);
  cp_tile(st + 16384, Alo + kt, lda);
  cp_tile(st + 32768, Bhi + kt, ldb);
  cp_tile(st + 49152, Blo + kt, ldb);
}

// ---- core: acc[128,128] += (Ahi+Alo)[128,K] @ ((Bhi+Blo)[128,K])^T ---------
// 8 warps: wm = wid>>2 (2 x 64 rows), wn = wid&3 (4 x 32 cols); warp 64x32
// 3-stage cp.async pipeline.
static __device__ __forceinline__ void hgemm_core(
    float (&acc)[4][4][4],
    const __nv_bfloat16* Ahi, const __nv_bfloat16* Alo, int lda,
    const __nv_bfloat16* Bhi, const __nv_bfloat16* Blo, int ldb, int K)
{
  const uint32_t sb = (smem_u32(dyn_smem) + 1023u) & ~1023u;
  const int tid = threadIdx.x, lane = tid&31, wid = tid>>5;
  const int wm = wid>>2, wn = wid&3;
  const int l7 = lane&7, sel = lane>>3;
  const int a_r = l7 + ((sel&1)<<3), a_g = sel>>1;
  const int b_r = l7 + ((sel>>1)<<3), b_g = sel&1;

  const int nc = K >> 6;    // nc >= 2 always in this kernel family
  cp_stage(sb, Ahi, Alo, lda, Bhi, Blo, ldb, 0);
  asm volatile("cp.async.commit_group;" ::: "memory");
  cp_stage(sb + STAGE_BYTES, Ahi, Alo, lda, Bhi, Blo, ldb, 64);
  asm volatile("cp.async.commit_group;" ::: "memory");

  uint32_t st = sb;
  for (int c = 0; c < nc; ++c){
    if (c + 2 < nc){
      uint32_t pf = sb;
      int s = c + 2 - ((c+2) >= 3 ? 3 : 0);          // (c+2)%3 via cheap form
      s = (c + 2) % 3;
      pf = sb + (uint32_t)s*STAGE_BYTES;
      cp_stage(pf, Ahi, Alo, lda, Bhi, Blo, ldb, (c+2)<<6);
      asm volatile("cp.async.commit_group;" ::: "memory");
      asm volatile("cp.async.wait_group 2;" ::: "memory");
    } else if (c + 1 < nc){
      asm volatile("cp.async.wait_group 1;" ::: "memory");
    } else {
      asm volatile("cp.async.wait_group 0;" ::: "memory");
    }
    __syncthreads();

#pragma unroll
    for (int ks = 0; ks < 4; ++ks){
      uint32_t bh[4][2], bl[4][2];
#pragma unroll
      for (int nn2 = 0; nn2 < 2; ++nn2){
        uint32_t bd = swz((uint32_t)(((wn*32 + nn2*16 + b_r)<<7) | ((ks*2 + b_g)<<4)));
        uint32_t r0, r1, r2, r3;
        ldsm4(st + 32768 + bd, r0, r1, r2, r3);
        bh[nn2*2][0]=r0; bh[nn2*2][1]=r1; bh[nn2*2+1][0]=r2; bh[nn2*2+1][1]=r3;
        ldsm4(st + 49152 + bd, r0, r1, r2, r3);
        bl[nn2*2][0]=r0; bl[nn2*2][1]=r1; bl[nn2*2+1][0]=r2; bl[nn2*2+1][1]=r3;
      }
#pragma unroll
      for (int mm = 0; mm < 4; ++mm){
        uint32_t ah[4], al[4];
        uint32_t ad = swz((uint32_t)(((wm*64 + mm*16 + a_r)<<7) | ((ks*2 + a_g)<<4)));
        ldsm4(st +         ad, ah[0], ah[1], ah[2], ah[3]);
        ldsm4(st + 16384 + ad, al[0], al[1], al[2], al[3]);
#pragma unroll
        for (int nn = 0; nn < 4; ++nn){
          float* a = acc[mm][nn];
          mma16816(a, ah, bh[nn]);
          mma16816(a, ah, bl[nn]);
          mma16816(a, al, bh[nn]);
        }
      }
    }
    if (c + 1 < nc) __syncthreads();
    st += STAGE_BYTES;
    if (st == sb + 3u*STAGE_BYTES) st = sb;
  }
}

static __device__ __forceinline__ void split_store2(
    __nv_bfloat16* H, __nv_bfloat16* L, size_t idx, float a, float b){
  __nv_bfloat16 ah = __float2bfloat16_rn(a), bh = __float2bfloat16_rn(b);
  __nv_bfloat16 alo = __float2bfloat16_rn(a - __bfloat162float(ah));
  __nv_bfloat16 blo = __float2bfloat16_rn(b - __bfloat162float(bh));
  *reinterpret_cast<__nv_bfloat162*>(H + idx) = __halves2bfloat162(ah, bh);
  *reinterpret_cast<__nv_bfloat162*>(L + idx) = __halves2bfloat162(alo, blo);
}

// ---------------- fp32 -> split bf16 ---------------------------------------
static __device__ __forceinline__ void split_body(
    const float* __restrict__ s, __nv_bfloat16* __restrict__ hi,
    __nv_bfloat16* __restrict__ lo, size_t i)
{
  float4 v = *reinterpret_cast<const float4*>(s + i);
  float f[4] = {v.x, v.y, v.z, v.w};
  __nv_bfloat16 h[4], l[4];
#pragma unroll
  for (int k = 0; k < 4; ++k){
    h[k] = __float2bfloat16_rn(f[k]);
    l[k] = __float2bfloat16_rn(f[k] - __bfloat162float(h[k]));
  }
  reinterpret_cast<__nv_bfloat162*>(hi + i)[0] = __halves2bfloat162(h[0], h[1]);
  reinterpret_cast<__nv_bfloat162*>(hi + i)[1] = __halves2bfloat162(h[2], h[3]);
  reinterpret_cast<__nv_bfloat162*>(lo + i)[0] = __halves2bfloat162(l[0], l[1]);
  reinterpret_cast<__nv_bfloat162*>(lo + i)[1] = __halves2bfloat162(l[2], l[3]);
}
__global__ __launch_bounds__(256) void split_x(const float* __restrict__ x){
  split_body(x, g_xhi, g_xlo, ((size_t)blockIdx.x*256 + threadIdx.x)*4);
}
__global__ __launch_bounds__(256) void split_w(
    const float* __restrict__ Wq, const float* __restrict__ Wk,
    const float* __restrict__ Wv, const float* __restrict__ Wo)
{
  const int z = blockIdx.y;
  const float* src = (z==0)?Wq:(z==1)?Wk:(z==2)?Wv:Wo;
  split_body(src, g_Whi + (size_t)z*C_*C_, g_Wlo + (size_t)z*C_*C_,
             ((size_t)blockIdx.x*256 + threadIdx.x)*4);
}

// ---------------- GEMM kernels ----------------------------------------------
__global__ __launch_bounds__(256, 1) void qkv_tc()
{
  const int z = blockIdx.z, m0 = blockIdx.y<<7, n0 = blockIdx.x<<7;
  const size_t wo = (size_t)z*C_*C_;
  float acc[4][4][4] = {};
  hgemm_core(acc, g_xhi + (size_t)m0*C_, g_xlo + (size_t)m0*C_, C_,
             g_Whi + wo + (size_t)n0*C_, g_Wlo + wo + (size_t)n0*C_, C_, C_);

  const int lane = threadIdx.x&31, wid = threadIdx.x>>5;
  const int wm = wid>>2, wn = wid&3;
  const int rb = lane>>2, cb = (lane&3)*2;

  if (z == 2){
    // V: stage transposed tile [c][t] in smem, then coalesced global writes
    __syncthreads();
    __nv_bfloat16* sh = reinterpret_cast<__nv_bfloat16*>(dyn_smem);
    __nv_bfloat16* sl = sh + 128*128;
#pragma unroll
    for (int mm = 0; mm < 4; ++mm)
#pragma unroll
      for (int nn = 0; nn < 4; ++nn){
        const int tl = wm*64 + mm*16 + rb;        // local t (row)
        const int cl = wn*32 + nn*8 + cb;         // local c (col)
        const float* a = acc[mm][nn];
#pragma unroll
        for (int u = 0; u < 4; ++u){
          const int tt = tl + (u>>1)*8;
          const int ccl = cl + (u&1);
          float v = a[u];
          __nv_bfloat16 h = __float2bfloat16_rn(v);
          sh[ccl*128 + tt] = h;
          sl[ccl*128 + tt] = __float2bfloat16_rn(v - __bfloat162float(h));
        }
      }
    __syncthreads();
    const int b = m0 >> 12, ml0 = m0 & (T_-1);
    const int tid = threadIdx.x;
    const int plane = tid >> 7, c = tid & 127;
    const __nv_bfloat16* srcrow = (plane ? sl : sh) + c*128;
    __nv_bfloat16* dst = (plane ? g_Vtlo : g_Vthi) + ((size_t)b*C_ + n0 + c)*T_ + ml0;
#pragma unroll
    for (int u = 0; u < 16; ++u)
      reinterpret_cast<uint4*>(dst)[u] = reinterpret_cast<const uint4*>(srcrow)[u];
    return;
  }

  __nv_bfloat16* H = (z == 0) ? g_Qhi : g_Khi;
  __nv_bfloat16* L = (z == 0) ? g_Qlo : g_Klo;
#pragma unroll
  for (int mm = 0; mm < 4; ++mm)
#pragma unroll
    for (int nn = 0; nn < 4; ++nn){
      const int r  = m0 + wm*64 + mm*16 + rb;
      const int cc = n0 + wn*32 + nn*8 + cb;
      const float* a = acc[mm][nn];
      size_t base = (size_t)r*C_ + cc;
      split_store2(H, L, base,          a[0], a[1]);
      split_store2(H, L, base + 8*C_,   a[2], a[3]);
    }
}

__global__ __launch_bounds__(256, 1) void scores_tc()
{
  if (blockIdx.x > blockIdx.y) return;               // fully-masked tile
  const int bz = blockIdx.z, m0 = blockIdx.y<<7, n0 = blockIdx.x<<7;
  const size_t qb = ((size_t)bz*T_ + m0)*C_;
  const size_t kb = ((size_t)bz*T_ + n0)*C_;
  float acc[4][4][4] = {};
  hgemm_core(acc, g_Qhi + qb, g_Qlo + qb, C_, g_Khi + kb, g_Klo + kb, C_, C_);

  const int lane = threadIdx.x&31, wid = threadIdx.x>>5;
  const int wm = wid>>2, wn = wid&3;
  const int rb = lane>>2, cb = (lane&3)*2;
#pragma unroll
  for (int mm = 0; mm < 4; ++mm)
#pragma unroll
    for (int nn = 0; nn < 4; ++nn){
      const int r  = m0 + wm*64 + mm*16 + rb;
      const int cc = n0 + wn*32 + nn*8 + cb;
      const float* a = acc[mm][nn];
      float* p = g_S + ((size_t)bz*T_ + r)*T_ + cc;
      *reinterpret_cast<float2*>(p)            = make_float2(a[0], a[1]);
      *reinterpret_cast<float2*>(p + 8ull*T_)  = make_float2(a[2], a[3]);
    }
}

__global__ __launch_bounds__(256, 1) void pv_tc()
{
  const int bz = blockIdx.z, m0 = blockIdx.y<<7, n0 = blockIdx.x<<7;
  const int K  = m0 + 128;
  const size_t pb = ((size_t)bz*T_ + m0)*T_;
  const size_t vb = ((size_t)bz*C_ + n0)*T_;
  float acc[4][4][4] = {};
  hgemm_core(acc, g_Phi + pb, g_Plo + pb, T_, g_Vthi + vb, g_Vtlo + vb, T_, K);

  const int lane = threadIdx.x&31, wid = threadIdx.x>>5;
  const int wm = wid>>2, wn = wid&3;
  const int rb = lane>>2, cb = (lane&3)*2;
#pragma unroll
  for (int mm = 0; mm < 4; ++mm)
#pragma unroll
    for (int nn = 0; nn < 4; ++nn){
      const int r  = m0 + wm*64 + mm*16 + rb;
      const int cc = n0 + wn*32 + nn*8 + cb;
      const float* a = acc[mm][nn];
      size_t base = ((size_t)bz*T_ + r)*C_ + cc;
      split_store2(g_AOhi, g_AOlo, base,        a[0], a[1]);
      split_store2(g_AOhi, g_AOlo, base + 8*C_, a[2], a[3]);
    }
}

__global__ __launch_bounds__(256, 1) void out_tc(const float* __restrict__ bo,
                                                 float* __restrict__ out)
{
  const int m0 = blockIdx.y<<7, n0 = blockIdx.x<<7;
  const size_t wo = (size_t)3*C_*C_;
  float acc[4][4][4] = {};
  hgemm_core(acc, g_AOhi + (size_t)m0*C_, g_AOlo + (size_t)m0*C_, C_,
             g_Whi + wo + (size_t)n0*C_, g_Wlo + wo + (size_t)n0*C_, C_, C_);

  const int lane = threadIdx.x&31, wid = threadIdx.x>>5;
  const int wm = wid>>2, wn = wid&3;
  const int rb = lane>>2, cb = (lane&3)*2;
#pragma unroll
  for (int mm = 0; mm < 4; ++mm)
#pragma unroll
    for (int nn = 0; nn < 4; ++nn){
      const int r  = m0 + wm*64 + mm*16 + rb;
      const int cc = n0 + wn*32 + nn*8 + cb;
      const float* a = acc[mm][nn];
      const float b0 = bo[cc], b1 = bo[cc+1];
      float* p = out + (size_t)r*C_ + cc;
      *reinterpret_cast<float2*>(p)          = make_float2(a[0]+b0, a[1]+b1);
      *reinterpret_cast<float2*>(p + 8*C_)   = make_float2(a[2]+b0, a[3]+b1);
    }
}

// ---------------- softmax: mask + scale + split-bf16 P ----------------------
__global__ __launch_bounds__(256) void softmax_k()
{
  const int gr = blockIdx.x;                 // 0..MT-1
  const int b  = gr >> 12, r = gr & (T_-1);
  const float* src = g_S + ((size_t)b*T_ + r)*T_;
  __nv_bfloat16* ph = g_Phi + ((size_t)b*T_ + r)*T_;
  __nv_bfloat16* pl = g_Plo + ((size_t)b*T_ + r)*T_;
  const int tid = threadIdx.x;
  const int nv  = r + 1;
  const int kmax = ((r >> 7) + 1) << 7;      // zero-pad to 128 (pv K granularity)
  const float scale = 0.03125f;              // 1/sqrt(1024)
  __shared__ float red[256];

  float m = __int_as_float(0xff800000);
  for (int c = tid; c < nv; c += 256) m = fmaxf(m, src[c]);
  red[tid] = m; __syncthreads();
  for (int s = 128; s > 0; s >>= 1){
    if (tid < s) red[tid] = fmaxf(red[tid], red[tid + s]);
    __syncthreads();
  }
  m = red[0]; __syncthreads();

  float sum = 0.f;
  for (int c = tid; c < nv; c += 256) sum += __expf((src[c] - m) * scale);
  red[tid] = sum; __syncthreads();
  for (int s = 128; s > 0; s >>= 1){
    if (tid < s) red[tid] += red[tid + s];
    __syncthreads();
  }
  const float inv = 1.f / red[0];

  for (int c = tid; c < kmax; c += 256){
    float p = (c < nv) ? __expf((src[c] - m) * scale) * inv : 0.f;
    __nv_bfloat16 h = __float2bfloat16_rn(p);
    ph[c] = h;
    pl[c] = __float2bfloat16_rn(p - __bfloat162float(h));
  }
}

// ---------------- launch -----------------------------------------------------
extern "C" void kernel_launch(void* const* d_in, const int* in_sizes, int n_in,
                              void* d_out, int out_size)
{
  const float* x  = (const float*)d_in[0];
  const float* Wq = (const float*)d_in[1];
  const float* Wk = (const float*)d_in[2];
  const float* Wv = (const float*)d_in[3];
  const float* Wo = (const float*)d_in[4];
  const float* bo = (const float*)d_in[5];
  float* out = (float*)d_out;
  (void)in_sizes; (void)n_in; (void)out_size;

  cudaFuncSetAttribute(qkv_tc,    cudaFuncAttributeMaxDynamicSharedMemorySize, SMEM_DYN);
  cudaFuncSetAttribute(scores_tc, cudaFuncAttributeMaxDynamicSharedMemorySize, SMEM_DYN);
  cudaFuncSetAttribute(pv_tc,     cudaFuncAttributeMaxDynamicSharedMemorySize, SMEM_DYN);
  cudaFuncSetAttribute(out_tc,    cudaFuncAttributeMaxDynamicSharedMemorySize, SMEM_DYN);

  split_x<<<(size_t)MT_*C_/1024, 256>>>(x);
  split_w<<<dim3(C_*C_/1024, 4), 256>>>(Wq, Wk, Wv, Wo);

  qkv_tc   <<<dim3(C_/128, MT_/128, 3), 256, SMEM_DYN>>>();
  scores_tc<<<dim3(T_/128, T_/128, B_), 256, SMEM_DYN>>>();
  softmax_k<<<MT_, 256>>>();
  pv_tc    <<<dim3(C_/128, T_/128, B_), 256, SMEM_DYN>>>();
  out_tc   <<<dim3(C_/128, MT_/128, 1), 256, SMEM_DYN>>>(bo, out);
}